// round 12
// baseline (speedup 1.0000x reference)
#include <cuda_runtime.h>
#include <cuda_bf16.h>
#include <cstdint>

#define BN 8
#define TT 4096
#define CI 1024
#define CO 1024
#define QP 127.0f

// ---------------- scratch (device globals; no allocation) ----------------
__device__ __nv_bfloat16 g_Xbf[(size_t)BN * TT * CI];   // quantized activations (bf16 ints)
__device__ __nv_bfloat16 g_Wbf[(size_t)3 * CO * CI];    // ternary weights [k][o][i]
__device__ float  g_mu[BN * TT];
__device__ float  g_rstd[BN * TT];
__device__ float  g_absmax[BN * CI];
__device__ float  g_wpart[512];
__device__ float  g_beta[1];

// ---------------- helpers ----------------
__device__ __forceinline__ void cp16(void* dst, const void* src, bool pred) {
    unsigned d = (unsigned)__cvta_generic_to_shared(dst);
    int sz = pred ? 16 : 0;
    asm volatile("cp.async.cg.shared.global [%0], [%1], 16, %2;\n"
                 :: "r"(d), "l"(src), "r"(sz));
}

__device__ __forceinline__ void mma_bf(float* c, const unsigned* a, const unsigned* b) {
    asm volatile(
        "mma.sync.aligned.m16n8k16.row.col.f32.bf16.bf16.f32 "
        "{%0,%1,%2,%3}, {%4,%5,%6,%7}, {%8,%9}, {%0,%1,%2,%3};\n"
        : "+f"(c[0]), "+f"(c[1]), "+f"(c[2]), "+f"(c[3])
        : "r"(a[0]), "r"(a[1]), "r"(a[2]), "r"(a[3]),
          "r"(b[0]), "r"(b[1]));
}

__device__ __forceinline__ void ldsm4(unsigned* r, unsigned saddr) {
    asm volatile("ldmatrix.sync.aligned.m8n8.x4.shared.b16 {%0,%1,%2,%3}, [%4];\n"
                 : "=r"(r[0]), "=r"(r[1]), "=r"(r[2]), "=r"(r[3]) : "r"(saddr));
}

// ---------------- kernel: zero the absmax buffer ----------------
__global__ void k_zero() {
    int i = blockIdx.x * 256 + threadIdx.x;
    if (i < BN * CI) g_absmax[i] = 0.f;
}

// ---------------- kernel: fused LN-stats (blocks 0..511) + weight-abs
//                  partial sums (blocks 512..1023), 128 threads each --------
#define RPW 16
__global__ void __launch_bounds__(128) k_pre(const float* __restrict__ x,
                                             const float* __restrict__ gam,
                                             const float* __restrict__ bet,
                                             const float* __restrict__ W) {
    const int tid  = threadIdx.x;
    const int lane = tid & 31, w = tid >> 5;

    if (blockIdx.x >= 512) {
        const int wb = blockIdx.x - 512;
        float s = 0.f;
        for (int i = wb * 128 + tid; i < CO * CI * 3; i += 512 * 128)
            s += fabsf(W[i]);
        #pragma unroll
        for (int o = 16; o; o >>= 1) s += __shfl_xor_sync(0xffffffffu, s, o);
        __shared__ float ws[4];
        if (lane == 0) ws[w] = s;
        __syncthreads();
        if (tid == 0)
            g_wpart[wb] = ws[0] + ws[1] + ws[2] + ws[3];
        return;
    }

    __shared__ unsigned smax[CI];
    for (int i = tid; i < CI; i += 128) smax[i] = 0u;
    __syncthreads();

    const int row0 = blockIdx.x * 64 + w * RPW;
    const int b    = row0 >> 12;

    float4 g4[8], b4[8];
    #pragma unroll
    for (int j = 0; j < 8; ++j) {
        g4[j] = *(const float4*)(gam + j * 128 + lane * 4);
        b4[j] = *(const float4*)(bet + j * 128 + lane * 4);
    }
    float4 mx[8];
    #pragma unroll
    for (int j = 0; j < 8; ++j) mx[j] = make_float4(0.f, 0.f, 0.f, 0.f);

    for (int r = 0; r < RPW; ++r) {
        const int row = row0 + r;
        const float* xr = x + (size_t)row * CI;
        float4 v[8];
        #pragma unroll
        for (int j = 0; j < 8; ++j)
            v[j] = *(const float4*)(xr + j * 128 + lane * 4);

        float s = 0.f, ss = 0.f;
        #pragma unroll
        for (int j = 0; j < 8; ++j) {
            s  += v[j].x + v[j].y + v[j].z + v[j].w;
            ss += v[j].x * v[j].x + v[j].y * v[j].y
                + v[j].z * v[j].z + v[j].w * v[j].w;
        }
        #pragma unroll
        for (int o = 16; o; o >>= 1) {
            s  += __shfl_xor_sync(0xffffffffu, s, o);
            ss += __shfl_xor_sync(0xffffffffu, ss, o);
        }
        const float mu  = s * (1.f / CI);
        const float var = ss * (1.f / CI) - mu * mu;
        const float rs  = rsqrtf(var + 1e-5f);
        if (lane == 0) { g_mu[row] = mu; g_rstd[row] = rs; }

        #pragma unroll
        for (int j = 0; j < 8; ++j) {
            mx[j].x = fmaxf(mx[j].x, fabsf((v[j].x - mu) * rs * g4[j].x + b4[j].x));
            mx[j].y = fmaxf(mx[j].y, fabsf((v[j].y - mu) * rs * g4[j].y + b4[j].y));
            mx[j].z = fmaxf(mx[j].z, fabsf((v[j].z - mu) * rs * g4[j].z + b4[j].z));
            mx[j].w = fmaxf(mx[j].w, fabsf((v[j].w - mu) * rs * g4[j].w + b4[j].w));
        }
    }

    #pragma unroll
    for (int j = 0; j < 8; ++j) {
        const int c = j * 128 + lane * 4;
        atomicMax(&smax[c + 0], __float_as_uint(mx[j].x));
        atomicMax(&smax[c + 1], __float_as_uint(mx[j].y));
        atomicMax(&smax[c + 2], __float_as_uint(mx[j].z));
        atomicMax(&smax[c + 3], __float_as_uint(mx[j].w));
    }
    __syncthreads();
    for (int i = tid; i < CI; i += 128)
        atomicMax((unsigned*)&g_absmax[b * CI + i], smax[i]);
}

// ---------------- kernel: weight quant (fused beta finalize) ---------------
__global__ void __launch_bounds__(256) k_wquant(const float* __restrict__ W) {
    const int tid = threadIdx.x;
    __shared__ float ws[8];
    __shared__ float sbeta;

    float s = g_wpart[tid] + g_wpart[tid + 256];
    #pragma unroll
    for (int o = 16; o; o >>= 1) s += __shfl_xor_sync(0xffffffffu, s, o);
    if ((tid & 31) == 0) ws[tid >> 5] = s;
    __syncthreads();
    if (tid == 0) {
        float t = 0.f;
        for (int i = 0; i < 8; ++i) t += ws[i];
        float beta = fmaxf(t / (float)(CO * CI * 3), 1e-5f);
        sbeta = beta;
        if (blockIdx.x == 0) g_beta[0] = beta;
    }
    __syncthreads();
    const float rb = 1.f / sbeta;

    const int idx = (blockIdx.x * 256 + tid) * 4;
    const float4* Wv = (const float4*)(W + (size_t)idx * 3);
    float4 w0 = Wv[0], w1 = Wv[1], w2 = Wv[2];

    auto tern = [&](float v) -> float {
        v *= rb;
        return rintf(fminf(fmaxf(v, -1.f), 1.f));
    };
    __nv_bfloat162 p0a, p0b, p1a, p1b, p2a, p2b;
    p0a.x = __float2bfloat16(tern(w0.x)); p0a.y = __float2bfloat16(tern(w0.w));
    p0b.x = __float2bfloat16(tern(w1.z)); p0b.y = __float2bfloat16(tern(w2.y));
    p1a.x = __float2bfloat16(tern(w0.y)); p1a.y = __float2bfloat16(tern(w1.x));
    p1b.x = __float2bfloat16(tern(w1.w)); p1b.y = __float2bfloat16(tern(w2.z));
    p2a.x = __float2bfloat16(tern(w0.z)); p2a.y = __float2bfloat16(tern(w1.y));
    p2b.x = __float2bfloat16(tern(w2.x)); p2b.y = __float2bfloat16(tern(w2.w));

    __nv_bfloat162* d0 = (__nv_bfloat162*)&g_Wbf[idx];
    __nv_bfloat162* d1 = (__nv_bfloat162*)&g_Wbf[(size_t)(CO * CI) + idx];
    __nv_bfloat162* d2 = (__nv_bfloat162*)&g_Wbf[(size_t)2 * (CO * CI) + idx];
    d0[0] = p0a; d0[1] = p0b;
    d1[0] = p1a; d1[1] = p1b;
    d2[0] = p2a; d2[1] = p2b;
}

// ---------------- kernel: activation quant, 8 rows/block -------------------
#define ARPB 8
__global__ void __launch_bounds__(256) k_aquant(const float* __restrict__ x,
                                                const float* __restrict__ gam,
                                                const float* __restrict__ bet) {
    const int tid  = threadIdx.x;
    const int row0 = blockIdx.x * ARPB;
    const int b    = row0 >> 12;
    const int c    = tid * 4;

    const float4 g4 = *(const float4*)(gam + c);
    const float4 b4 = *(const float4*)(bet + c);
    const float4 am = *(const float4*)(g_absmax + b * CI + c);
    float4 sc;
    sc.x = QP / fmaxf(am.x, 1e-5f);
    sc.y = QP / fmaxf(am.y, 1e-5f);
    sc.z = QP / fmaxf(am.z, 1e-5f);
    sc.w = QP / fmaxf(am.w, 1e-5f);

    #pragma unroll
    for (int r = 0; r < ARPB; ++r) {
        const int row = row0 + r;
        const float mu = __ldg(&g_mu[row]);
        const float rs = __ldg(&g_rstd[row]);
        float4 v = *(const float4*)(x + (size_t)row * CI + c);

        float q0 = fminf(fmaxf(rintf(((v.x - mu) * rs * g4.x + b4.x) * sc.x), -QP), QP);
        float q1 = fminf(fmaxf(rintf(((v.y - mu) * rs * g4.y + b4.y) * sc.y), -QP), QP);
        float q2 = fminf(fmaxf(rintf(((v.z - mu) * rs * g4.z + b4.z) * sc.z), -QP), QP);
        float q3 = fminf(fmaxf(rintf(((v.w - mu) * rs * g4.w + b4.w) * sc.w), -QP), QP);

        __nv_bfloat162 q01, q23;
        q01.x = __float2bfloat16(q0); q01.y = __float2bfloat16(q1);
        q23.x = __float2bfloat16(q2); q23.y = __float2bfloat16(q3);
        __nv_bfloat162* dst = (__nv_bfloat162*)&g_Xbf[(size_t)row * CI + c];
        dst[0] = q01; dst[1] = q23;
    }
}

// ---------------- conv bf16 GEMM: 64x64 warp tiles @ 8 warps/SM ------------
// CTA 128(o) x 128(t), 128 threads (4 warps, 2x2), 2 CTAs/SM.
// K: 64 chunks of 16 elems. 4-stage ring, 1 sync/iter.
// ldsm bytes/mma = 128 (vs 192 in R8) while keeping 8 warps/SM (vs 4 in R6).
#define ASTRIDE 48
#define A_TAP   6144
#define B_OFF   18432
#define STAGE_B 24672
#define NSTAGE  4
#define SMEM_DYN (NSTAGE * STAGE_B + 512)

__global__ void __launch_bounds__(128, 2) k_conv(float* __restrict__ out) {
    extern __shared__ char dsm[];
    const unsigned sbase = (unsigned)__cvta_generic_to_shared(dsm);

    const int tid = threadIdx.x;
    const int t0  = blockIdx.x * 128;
    const int o0  = blockIdx.y * 128;
    const int b   = blockIdx.z;

    float* epi = (float*)(dsm + NSTAGE * STAGE_B);
    epi[tid] = g_beta[0] * fmaxf(g_absmax[b * CI + o0 + tid], 1e-5f) * (1.f / QP);

    const int warp = tid >> 5, lane = tid & 31;
    const int wm = warp & 1, wn = warp >> 1;      // 2x2 warp grid, 64(o) x 64(t)
    const int g  = lane >> 2, tg = lane & 3;

    const unsigned alane = (unsigned)(((lane & 7) + 8 * ((lane >> 3) & 1)) * ASTRIDE
                                      + ((lane >> 4) << 4));
    const unsigned blane = (unsigned)(((lane & 7) + 8 * (lane >> 4)) * ASTRIDE
                                      + (((lane >> 3) & 1) << 4));

    float acc[4][8][4];
    #pragma unroll
    for (int mi = 0; mi < 4; ++mi)
        #pragma unroll
        for (int ni = 0; ni < 8; ++ni)
            #pragma unroll
            for (int r = 0; r < 4; ++r) acc[mi][ni][r] = 0.f;

    auto issue = [&](int chunk, int s) {
        char* st = dsm + s * STAGE_B;
        const int i0 = chunk << 4;                  // 16 bf16 elems per chunk
        #pragma unroll
        for (int j = 0; j < 9; ++j) {
            const int idx = tid + j * 128;
            if (idx < 768) {                  // A: 3 taps x 128 rows x 2 x16B
                const int tap = idx >> 8;
                const int rr  = (idx >> 1) & 127;
                const int off = (idx & 1) << 3;     // elems (8 bf16 = 16B)
                cp16(st + tap * A_TAP + rr * ASTRIDE + (off << 1),
                     g_Wbf + (size_t)tap * (CO * CI) + (size_t)(o0 + rr) * CI + i0 + off,
                     true);
            } else if (idx < 1028) {          // B: 130 halo rows x 2 x16B
                const int bi = idx - 768;
                const int rr = bi >> 1;
                const int off = (bi & 1) << 3;
                const int tg2 = t0 - 1 + rr;
                const bool p = (unsigned)tg2 < (unsigned)TT;
                cp16(st + B_OFF + rr * ASTRIDE + (off << 1),
                     g_Xbf + ((size_t)b * TT + (p ? tg2 : 0)) * CI + i0 + off, p);
            }
        }
    };

    auto compute = [&](int s) {
        const unsigned st = sbase + s * STAGE_B;
        #pragma unroll
        for (int tap = 0; tap < 3; ++tap) {
            unsigned afr[4][4];
            #pragma unroll
            for (int mi = 0; mi < 4; ++mi)
                ldsm4(afr[mi], st + tap * A_TAP
                          + (unsigned)((wm * 64 + mi * 16) * ASTRIDE) + alane);
            #pragma unroll
            for (int nj = 0; nj < 4; ++nj) {
                unsigned bfr[4];
                ldsm4(bfr, st + B_OFF
                          + (unsigned)((wn * 64 + nj * 16 + tap) * ASTRIDE) + blane);
                #pragma unroll
                for (int mi = 0; mi < 4; ++mi) {
                    mma_bf(acc[mi][2 * nj + 0], afr[mi], bfr + 0);
                    mma_bf(acc[mi][2 * nj + 1], afr[mi], bfr + 2);
                }
            }
        }
    };

    issue(0, 0); asm volatile("cp.async.commit_group;\n");
    issue(1, 1); asm volatile("cp.async.commit_group;\n");
    issue(2, 2); asm volatile("cp.async.commit_group;\n");

    #pragma unroll 1
    for (int it = 0; it <= 60; ++it) {
        asm volatile("cp.async.wait_group 2;\n");
        __syncthreads();
        compute(it & 3);
        issue(it + 3, (it + 3) & 3);
        asm volatile("cp.async.commit_group;\n");
    }
    asm volatile("cp.async.wait_group 2;\n");
    __syncthreads();
    compute(61 & 3);
    asm volatile("cp.async.wait_group 1;\n");
    __syncthreads();
    compute(62 & 3);
    asm volatile("cp.async.wait_group 0;\n");
    __syncthreads();
    compute(63 & 3);

    // ---- epilogue: transpose C[o][t] -> out[b][t][o] via SMEM, scale ----
    float* outb = (float*)dsm;                // 64 t x 132 o floats
    #pragma unroll
    for (int h = 0; h < 2; ++h) {
        __syncthreads();
        if (wn == h) {
            #pragma unroll
            for (int mi = 0; mi < 4; ++mi)
                #pragma unroll
                for (int ni = 0; ni < 8; ++ni)
                    #pragma unroll
                    for (int r = 0; r < 4; ++r) {
                        const int ro = wm * 64 + mi * 16 + g + 8 * (r >> 1);
                        const int ct = ni * 8 + 2 * tg + (r & 1);
                        outb[ct * 132 + ro] = acc[mi][ni][r];
                    }
        }
        __syncthreads();
        #pragma unroll
        for (int j = 0; j < 16; ++j) {
            const int f  = tid + j * 128;
            const int tl = f >> 5;
            const int o4 = (f & 31) << 2;
            float4 v = *(float4*)&outb[tl * 132 + o4];
            v.x *= epi[o4 + 0]; v.y *= epi[o4 + 1];
            v.z *= epi[o4 + 2]; v.w *= epi[o4 + 3];
            *(float4*)(out + ((size_t)(b * TT + t0 + h * 64 + tl)) * CO + o0 + o4) = v;
        }
    }
}

// ---------------- launch ----------------
extern "C" void kernel_launch(void* const* d_in, const int* in_sizes, int n_in,
                              void* d_out, int out_size) {
    const float* x   = (const float*)d_in[0];
    const float* gam = (const float*)d_in[1];
    const float* bet = (const float*)d_in[2];
    const float* W   = (const float*)d_in[3];
    float* out = (float*)d_out;

    cudaFuncSetAttribute(k_conv, cudaFuncAttributeMaxDynamicSharedMemorySize, SMEM_DYN);

    k_zero<<<32, 256>>>();
    k_pre<<<1024, 128>>>(x, gam, bet, W);          // LN stats + weight-abs
    k_wquant<<<1024, 256>>>(W);                    // beta finalize + quant
    k_aquant<<<(BN * TT) / ARPB, 256>>>(x, gam, bet);
    k_conv<<<dim3(TT / 128, CO / 128, BN), 128, SMEM_DYN>>>(out);
}

// round 14
// speedup vs baseline: 1.0506x; 1.0506x over previous
#include <cuda_runtime.h>
#include <cuda_bf16.h>
#include <cstdint>

#define BN 8
#define TT 4096
#define CI 1024
#define CO 1024
#define QP 127.0f

// ---------------- scratch (device globals; no allocation) ----------------
__device__ __nv_bfloat16 g_Xbf[(size_t)BN * TT * CI];   // quantized activations (bf16 ints)
__device__ __nv_bfloat16 g_Wbf[(size_t)3 * CO * CI];    // ternary weights [k][o][i]
__device__ float  g_mu[BN * TT];
__device__ float  g_rstd[BN * TT];
__device__ float  g_absmax[BN * CI];
__device__ float  g_wpart[512];
__device__ float  g_beta[1];

// ---------------- helpers ----------------
__device__ __forceinline__ void cp16(void* dst, const void* src, bool pred) {
    unsigned d = (unsigned)__cvta_generic_to_shared(dst);
    int sz = pred ? 16 : 0;
    asm volatile("cp.async.cg.shared.global [%0], [%1], 16, %2;\n"
                 :: "r"(d), "l"(src), "r"(sz));
}

__device__ __forceinline__ void mma_bf(float* c, const unsigned* a, const unsigned* b) {
    asm volatile(
        "mma.sync.aligned.m16n8k16.row.col.f32.bf16.bf16.f32 "
        "{%0,%1,%2,%3}, {%4,%5,%6,%7}, {%8,%9}, {%0,%1,%2,%3};\n"
        : "+f"(c[0]), "+f"(c[1]), "+f"(c[2]), "+f"(c[3])
        : "r"(a[0]), "r"(a[1]), "r"(a[2]), "r"(a[3]),
          "r"(b[0]), "r"(b[1]));
}

__device__ __forceinline__ void ldsm4(unsigned* r, unsigned saddr) {
    asm volatile("ldmatrix.sync.aligned.m8n8.x4.shared.b16 {%0,%1,%2,%3}, [%4];\n"
                 : "=r"(r[0]), "=r"(r[1]), "=r"(r[2]), "=r"(r[3]) : "r"(saddr));
}

// ---------------- kernel: zero the absmax buffer ----------------
__global__ void k_zero() {
    int i = blockIdx.x * 256 + threadIdx.x;
    if (i < BN * CI) g_absmax[i] = 0.f;
}

// ---------------- kernel: fused LN-stats (blocks 0..511) + weight-abs
//                  partial sums (blocks 512..1023), 128 threads each --------
#define RPW 16
__global__ void __launch_bounds__(128) k_pre(const float* __restrict__ x,
                                             const float* __restrict__ gam,
                                             const float* __restrict__ bet,
                                             const float* __restrict__ W) {
    const int tid  = threadIdx.x;
    const int lane = tid & 31, w = tid >> 5;

    if (blockIdx.x >= 512) {
        const int wb = blockIdx.x - 512;
        float s = 0.f;
        for (int i = wb * 128 + tid; i < CO * CI * 3; i += 512 * 128)
            s += fabsf(W[i]);
        #pragma unroll
        for (int o = 16; o; o >>= 1) s += __shfl_xor_sync(0xffffffffu, s, o);
        __shared__ float ws[4];
        if (lane == 0) ws[w] = s;
        __syncthreads();
        if (tid == 0)
            g_wpart[wb] = ws[0] + ws[1] + ws[2] + ws[3];
        return;
    }

    __shared__ unsigned smax[CI];
    for (int i = tid; i < CI; i += 128) smax[i] = 0u;
    __syncthreads();

    const int row0 = blockIdx.x * 64 + w * RPW;
    const int b    = row0 >> 12;

    float4 g4[8], b4[8];
    #pragma unroll
    for (int j = 0; j < 8; ++j) {
        g4[j] = *(const float4*)(gam + j * 128 + lane * 4);
        b4[j] = *(const float4*)(bet + j * 128 + lane * 4);
    }
    float4 mx[8];
    #pragma unroll
    for (int j = 0; j < 8; ++j) mx[j] = make_float4(0.f, 0.f, 0.f, 0.f);

    for (int r = 0; r < RPW; ++r) {
        const int row = row0 + r;
        const float* xr = x + (size_t)row * CI;
        float4 v[8];
        #pragma unroll
        for (int j = 0; j < 8; ++j)
            v[j] = *(const float4*)(xr + j * 128 + lane * 4);

        float s = 0.f, ss = 0.f;
        #pragma unroll
        for (int j = 0; j < 8; ++j) {
            s  += v[j].x + v[j].y + v[j].z + v[j].w;
            ss += v[j].x * v[j].x + v[j].y * v[j].y
                + v[j].z * v[j].z + v[j].w * v[j].w;
        }
        #pragma unroll
        for (int o = 16; o; o >>= 1) {
            s  += __shfl_xor_sync(0xffffffffu, s, o);
            ss += __shfl_xor_sync(0xffffffffu, ss, o);
        }
        const float mu  = s * (1.f / CI);
        const float var = ss * (1.f / CI) - mu * mu;
        const float rs  = rsqrtf(var + 1e-5f);
        if (lane == 0) { g_mu[row] = mu; g_rstd[row] = rs; }

        #pragma unroll
        for (int j = 0; j < 8; ++j) {
            mx[j].x = fmaxf(mx[j].x, fabsf((v[j].x - mu) * rs * g4[j].x + b4[j].x));
            mx[j].y = fmaxf(mx[j].y, fabsf((v[j].y - mu) * rs * g4[j].y + b4[j].y));
            mx[j].z = fmaxf(mx[j].z, fabsf((v[j].z - mu) * rs * g4[j].z + b4[j].z));
            mx[j].w = fmaxf(mx[j].w, fabsf((v[j].w - mu) * rs * g4[j].w + b4[j].w));
        }
    }

    #pragma unroll
    for (int j = 0; j < 8; ++j) {
        const int c = j * 128 + lane * 4;
        atomicMax(&smax[c + 0], __float_as_uint(mx[j].x));
        atomicMax(&smax[c + 1], __float_as_uint(mx[j].y));
        atomicMax(&smax[c + 2], __float_as_uint(mx[j].z));
        atomicMax(&smax[c + 3], __float_as_uint(mx[j].w));
    }
    __syncthreads();
    for (int i = tid; i < CI; i += 128)
        atomicMax((unsigned*)&g_absmax[b * CI + i], smax[i]);
}

// ---------------- kernel: fused activation quant + weight quant ------------
// blocks [0, 4096):    activation quant, 8 rows/block
// blocks [4096, 5120): weight quant (each re-reduces the 512 |W| partials)
#define ARPB 8
__global__ void __launch_bounds__(256) k_quant(const float* __restrict__ x,
                                               const float* __restrict__ gam,
                                               const float* __restrict__ bet,
                                               const float* __restrict__ W) {
    const int tid = threadIdx.x;

    if (blockIdx.x < (BN * TT) / ARPB) {
        // ---- activation quant ----
        const int row0 = blockIdx.x * ARPB;
        const int b    = row0 >> 12;
        const int c    = tid * 4;

        const float4 g4 = *(const float4*)(gam + c);
        const float4 b4 = *(const float4*)(bet + c);
        const float4 am = *(const float4*)(g_absmax + b * CI + c);
        float4 sc;
        sc.x = QP / fmaxf(am.x, 1e-5f);
        sc.y = QP / fmaxf(am.y, 1e-5f);
        sc.z = QP / fmaxf(am.z, 1e-5f);
        sc.w = QP / fmaxf(am.w, 1e-5f);

        #pragma unroll
        for (int r = 0; r < ARPB; ++r) {
            const int row = row0 + r;
            const float mu = __ldg(&g_mu[row]);
            const float rs = __ldg(&g_rstd[row]);
            float4 v = *(const float4*)(x + (size_t)row * CI + c);

            float q0 = fminf(fmaxf(rintf(((v.x - mu) * rs * g4.x + b4.x) * sc.x), -QP), QP);
            float q1 = fminf(fmaxf(rintf(((v.y - mu) * rs * g4.y + b4.y) * sc.y), -QP), QP);
            float q2 = fminf(fmaxf(rintf(((v.z - mu) * rs * g4.z + b4.z) * sc.z), -QP), QP);
            float q3 = fminf(fmaxf(rintf(((v.w - mu) * rs * g4.w + b4.w) * sc.w), -QP), QP);

            __nv_bfloat162 q01, q23;
            q01.x = __float2bfloat16(q0); q01.y = __float2bfloat16(q1);
            q23.x = __float2bfloat16(q2); q23.y = __float2bfloat16(q3);
            __nv_bfloat162* dst = (__nv_bfloat162*)&g_Xbf[(size_t)row * CI + c];
            dst[0] = q01; dst[1] = q23;
        }
    } else {
        // ---- weight quant (fused beta finalize) ----
        const int wb = blockIdx.x - (BN * TT) / ARPB;   // 0..1023
        __shared__ float ws[8];
        __shared__ float sbeta;

        float s = g_wpart[tid] + g_wpart[tid + 256];
        #pragma unroll
        for (int o = 16; o; o >>= 1) s += __shfl_xor_sync(0xffffffffu, s, o);
        if ((tid & 31) == 0) ws[tid >> 5] = s;
        __syncthreads();
        if (tid == 0) {
            float t = 0.f;
            for (int i = 0; i < 8; ++i) t += ws[i];
            float beta = fmaxf(t / (float)(CO * CI * 3), 1e-5f);
            sbeta = beta;
            if (wb == 0) g_beta[0] = beta;
        }
        __syncthreads();
        const float rb = 1.f / sbeta;

        const int idx = (wb * 256 + tid) * 4;           // 4 consecutive (o,i)
        const float4* Wv = (const float4*)(W + (size_t)idx * 3);
        float4 w0 = Wv[0], w1 = Wv[1], w2 = Wv[2];

        auto tern = [&](float v) -> float {
            v *= rb;
            return rintf(fminf(fmaxf(v, -1.f), 1.f));
        };
        __nv_bfloat162 p0a, p0b, p1a, p1b, p2a, p2b;
        p0a.x = __float2bfloat16(tern(w0.x)); p0a.y = __float2bfloat16(tern(w0.w));
        p0b.x = __float2bfloat16(tern(w1.z)); p0b.y = __float2bfloat16(tern(w2.y));
        p1a.x = __float2bfloat16(tern(w0.y)); p1a.y = __float2bfloat16(tern(w1.x));
        p1b.x = __float2bfloat16(tern(w1.w)); p1b.y = __float2bfloat16(tern(w2.z));
        p2a.x = __float2bfloat16(tern(w0.z)); p2a.y = __float2bfloat16(tern(w1.y));
        p2b.x = __float2bfloat16(tern(w2.x)); p2b.y = __float2bfloat16(tern(w2.w));

        __nv_bfloat162* d0 = (__nv_bfloat162*)&g_Wbf[idx];
        __nv_bfloat162* d1 = (__nv_bfloat162*)&g_Wbf[(size_t)(CO * CI) + idx];
        __nv_bfloat162* d2 = (__nv_bfloat162*)&g_Wbf[(size_t)2 * (CO * CI) + idx];
        d0[0] = p0a; d0[1] = p0b;
        d1[0] = p1a; d1[1] = p1b;
        d2[0] = p2a; d2[1] = p2b;
    }
}

// ---------------- conv bf16 GEMM, 4-stage ring, 1 sync/iter ----------------
// R11-exact config: 256 threads, 2x4 warps of 64(o) x 32(t).
// At the legacy-HMMA rate wall (rt_SMSP=12 -> ~3 cyc/warp-mma/SM).
#define ASTRIDE 48
#define A_TAP   6144
#define B_OFF   18432
#define STAGE_B 24672
#define NSTAGE  4
#define SMEM_DYN (NSTAGE * STAGE_B + 512)

__global__ void __launch_bounds__(256, 2) k_conv(float* __restrict__ out) {
    extern __shared__ char dsm[];
    const unsigned sbase = (unsigned)__cvta_generic_to_shared(dsm);

    const int tid = threadIdx.x;
    const int t0  = blockIdx.x * 128;
    const int o0  = blockIdx.y * 128;
    const int b   = blockIdx.z;

    float* epi = (float*)(dsm + NSTAGE * STAGE_B);
    if (tid < 128)
        epi[tid] = g_beta[0] * fmaxf(g_absmax[b * CI + o0 + tid], 1e-5f) * (1.f / QP);

    const int warp = tid >> 5, lane = tid & 31;
    const int wm = warp & 1, wn = warp >> 1;      // 2x4 warp grid, 64(o) x 32(t)
    const int g  = lane >> 2, tg = lane & 3;

    const unsigned alane = (unsigned)(((lane & 7) + 8 * ((lane >> 3) & 1)) * ASTRIDE
                                      + ((lane >> 4) << 4));
    const unsigned blane = (unsigned)(((lane & 7) + 8 * (lane >> 4)) * ASTRIDE
                                      + (((lane >> 3) & 1) << 4));

    float acc[4][4][4];
    #pragma unroll
    for (int mi = 0; mi < 4; ++mi)
        #pragma unroll
        for (int ni = 0; ni < 4; ++ni)
            #pragma unroll
            for (int r = 0; r < 4; ++r) acc[mi][ni][r] = 0.f;

    auto issue = [&](int chunk, int s) {
        char* st = dsm + s * STAGE_B;
        const int i0 = chunk << 4;                  // 16 bf16 elems per chunk
        #pragma unroll
        for (int j = 0; j < 5; ++j) {
            const int idx = tid + j * 256;
            if (idx < 768) {                  // A: 3 taps x 128 rows x 2 x16B
                const int tap = idx >> 8;
                const int rr  = (idx >> 1) & 127;
                const int off = (idx & 1) << 3;     // elems (8 bf16 = 16B)
                cp16(st + tap * A_TAP + rr * ASTRIDE + (off << 1),
                     g_Wbf + (size_t)tap * (CO * CI) + (size_t)(o0 + rr) * CI + i0 + off,
                     true);
            } else if (idx < 1028) {          // B: 130 halo rows x 2 x16B
                const int bi = idx - 768;
                const int rr = bi >> 1;
                const int off = (bi & 1) << 3;
                const int tg2 = t0 - 1 + rr;
                const bool p = (unsigned)tg2 < (unsigned)TT;
                cp16(st + B_OFF + rr * ASTRIDE + (off << 1),
                     g_Xbf + ((size_t)b * TT + (p ? tg2 : 0)) * CI + i0 + off, p);
            }
        }
    };

    auto compute = [&](int s) {
        const unsigned st = sbase + s * STAGE_B;
        #pragma unroll
        for (int tap = 0; tap < 3; ++tap) {
            unsigned afr[4][4];
            #pragma unroll
            for (int mi = 0; mi < 4; ++mi)
                ldsm4(afr[mi], st + tap * A_TAP
                          + (unsigned)((wm * 64 + mi * 16) * ASTRIDE) + alane);
            #pragma unroll
            for (int nj = 0; nj < 2; ++nj) {
                unsigned bfr[4];
                ldsm4(bfr, st + B_OFF
                          + (unsigned)((wn * 32 + nj * 16 + tap) * ASTRIDE) + blane);
                #pragma unroll
                for (int mi = 0; mi < 4; ++mi) {
                    mma_bf(acc[mi][2 * nj + 0], afr[mi], bfr + 0);
                    mma_bf(acc[mi][2 * nj + 1], afr[mi], bfr + 2);
                }
            }
        }
    };

    issue(0, 0); asm volatile("cp.async.commit_group;\n");
    issue(1, 1); asm volatile("cp.async.commit_group;\n");
    issue(2, 2); asm volatile("cp.async.commit_group;\n");

    #pragma unroll 1
    for (int it = 0; it <= 60; ++it) {
        asm volatile("cp.async.wait_group 2;\n");
        __syncthreads();
        compute(it & 3);
        issue(it + 3, (it + 3) & 3);
        asm volatile("cp.async.commit_group;\n");
    }
    asm volatile("cp.async.wait_group 2;\n");
    __syncthreads();
    compute(61 & 3);
    asm volatile("cp.async.wait_group 1;\n");
    __syncthreads();
    compute(62 & 3);
    asm volatile("cp.async.wait_group 0;\n");
    __syncthreads();
    compute(63 & 3);

    // ---- epilogue: transpose C[o][t] -> out[b][t][o] via SMEM, scale ----
    float* outb = (float*)dsm;                // 64 t x 132 o floats
    #pragma unroll
    for (int h = 0; h < 2; ++h) {
        __syncthreads();
        if ((wn >> 1) == h) {
            #pragma unroll
            for (int mi = 0; mi < 4; ++mi)
                #pragma unroll
                for (int ni = 0; ni < 4; ++ni)
                    #pragma unroll
                    for (int r = 0; r < 4; ++r) {
                        const int ro = wm * 64 + mi * 16 + g + 8 * (r >> 1);
                        const int ct = (wn & 1) * 32 + ni * 8 + 2 * tg + (r & 1);
                        outb[ct * 132 + ro] = acc[mi][ni][r];
                    }
        }
        __syncthreads();
        #pragma unroll
        for (int j = 0; j < 8; ++j) {
            const int f  = tid + j * 256;
            const int tl = f >> 5;
            const int o4 = (f & 31) << 2;
            float4 v = *(float4*)&outb[tl * 132 + o4];
            v.x *= epi[o4 + 0]; v.y *= epi[o4 + 1];
            v.z *= epi[o4 + 2]; v.w *= epi[o4 + 3];
            *(float4*)(out + ((size_t)(b * TT + t0 + h * 64 + tl)) * CO + o0 + o4) = v;
        }
    }
}

// ---------------- launch ----------------
extern "C" void kernel_launch(void* const* d_in, const int* in_sizes, int n_in,
                              void* d_out, int out_size) {
    const float* x   = (const float*)d_in[0];
    const float* gam = (const float*)d_in[1];
    const float* bet = (const float*)d_in[2];
    const float* W   = (const float*)d_in[3];
    float* out = (float*)d_out;

    cudaFuncSetAttribute(k_conv, cudaFuncAttributeMaxDynamicSharedMemorySize, SMEM_DYN);

    k_zero<<<32, 256>>>();
    k_pre<<<1024, 128>>>(x, gam, bet, W);               // LN stats + weight-abs
    k_quant<<<(BN * TT) / ARPB + 1024, 256>>>(x, gam, bet, W);  // aquant + wquant
    k_conv<<<dim3(TT / 128, CO / 128, BN), 256, SMEM_DYN>>>(out);
}